// round 17
// baseline (speedup 1.0000x reference)
#include <cuda_runtime.h>

// SoftTopKBottomK via Sinkhorn reformulation — warpgroup-per-row, named
// barriers, zero per-element transcendentals in the iteration, float4 I/O,
// deliberate phase-skew between the 4 independent warpgroups.
//
// Math: t_i = T_i * E with T_i = 2^{(0.25-x_i)*SC} precomputed once.
// Multiplicative potentials: E <- E*s*S2*rc, F <- F*s*S0*rc,
//   rc = 1/(S0*S2), s = S1/6, Q = QC*E*F.
// Per element per iter: t = T*E; d = t^2+t+Q; r = 1/d  (FMUL+FMA+RCP)
//   S0 = N - sum((t+Q)r), S2 = Q*sum(r), S1 = N - S0 - S2
// Output: out_i = r*(Q*g2 - t^2*g0), g_j = 512/S_j (final-pass state).
//
// R16: lambda MEASURED at 0.305 (rel_err 8.9e-7@10 -> 3.1e-5@7, ratio 35
// over 3 iters). ITERS=6 => predicted rel_err ~1.0e-4, 10x margin under
// the 1e-3 gate. Skew spacing trimmed 384->~265 cyc (still >= tail length)
// to cut the last group's one-time critical-path offset.

#define NCOLS   4096
#define THREADS 512
#define NGROUPS 4
#define GSIZE   128         // threads per warpgroup (one row each)
#define NQUAD   8           // float4s per thread: 128*8*4 = 4096
#define NPAIR   16          // packed f32 pairs per thread
#define ITERS   6
#define SKEWN   44          // dependent-FADD steps per group of skew

typedef unsigned long long u64;

__device__ __forceinline__ float ex2f(float x) {
    float y; asm("ex2.approx.f32 %0, %1;" : "=f"(y) : "f"(x)); return y;
}
__device__ __forceinline__ float rcpf(float x) {
    float y; asm("rcp.approx.f32 %0, %1;" : "=f"(y) : "f"(x)); return y;
}
__device__ __forceinline__ u64 pack2(float lo, float hi) {
    u64 r; asm("mov.b64 %0, {%1, %2};" : "=l"(r) : "f"(lo), "f"(hi)); return r;
}
__device__ __forceinline__ void unpack2(u64 v, float& lo, float& hi) {
    asm("mov.b64 {%0, %1}, %2;" : "=f"(lo), "=f"(hi) : "l"(v));
}
__device__ __forceinline__ u64 addx2(u64 a, u64 b) {
    u64 r; asm("add.rn.f32x2 %0, %1, %2;" : "=l"(r) : "l"(a), "l"(b)); return r;
}
__device__ __forceinline__ u64 mulx2(u64 a, u64 b) {
    u64 r; asm("mul.rn.f32x2 %0, %1, %2;" : "=l"(r) : "l"(a), "l"(b)); return r;
}
__device__ __forceinline__ u64 fmax2(u64 a, u64 b, u64 c) {
    u64 r; asm("fma.rn.f32x2 %0, %1, %2, %3;" : "=l"(r) : "l"(a), "l"(b), "l"(c)); return r;
}
__device__ __forceinline__ void gbar(int id) {
    asm volatile("bar.sync %0, %1;" :: "r"(id), "r"(GSIZE) : "memory");
}

__global__ void __launch_bounds__(THREADS, 1)
soft_topk_bottomk_kernel(const float* __restrict__ scores,
                         float* __restrict__ out, int rows)
{
    const int tid   = threadIdx.x;
    const int grp   = tid >> 7;          // warpgroup 0..3 (warp-aligned)
    const int gtid  = tid & (GSIZE - 1); // thread within group
    const int gwid  = gtid >> 5;         // warp within group 0..3
    const int lid   = tid & 31;
    const int barid = grp + 1;           // named barrier ids 1..4

    int rr = NGROUPS * blockIdx.x + grp;
    const int row = (rr < rows) ? rr : rows - 1;   // clamp; dup rows benign

    const float4* __restrict__ srow =
        (const float4*)(scores + (size_t)row * NCOLS);
    float4* __restrict__ orow = (float4*)(out + (size_t)row * NCOLS);

    // per-group smem: double-buffered 4-warp partials (sA, sR)
    __shared__ float2 red[2][NGROUPS][4];

    // ---- load row as float4 (8 LDG.128), group-local min/max ----
    float4 v4[NQUAD];
#pragma unroll
    for (int q = 0; q < NQUAD; q++) v4[q] = srow[gtid + q * GSIZE];

    float mn = v4[0].x, mx = v4[0].x;
#pragma unroll
    for (int q = 0; q < NQUAD; q++) {
        mn = fminf(mn, fminf(fminf(v4[q].x, v4[q].y), fminf(v4[q].z, v4[q].w)));
        mx = fmaxf(mx, fmaxf(fmaxf(v4[q].x, v4[q].y), fmaxf(v4[q].z, v4[q].w)));
    }
#pragma unroll
    for (int off = 16; off; off >>= 1) {
        mn = fminf(mn, __shfl_xor_sync(0xffffffffu, mn, off));
        mx = fmaxf(mx, __shfl_xor_sync(0xffffffffu, mx, off));
    }
    if (lid == 0) red[0][grp][gwid] = make_float2(mn, mx);
    gbar(barid);
#pragma unroll
    for (int w = 0; w < 4; w++) {
        float2 p = red[0][grp][w];
        mn = fminf(mn, p.x);
        mx = fmaxf(mx, p.y);
    }
    gbar(barid);   // fence reads before loop reuses red[0][grp]

    // ---- precompute T_i = 2^{(0.25 - x_i)*SC}, packed pairs ----
    const float SC = 14.426950408889634f;       // (1/eps)*log2(e), eps=0.1
    const float QC = 0.006737946999085467f;     // 2^{-0.5*SC} = e^{-5}
    const float inv = 1.0f / (mx - mn + 1e-12f);

    u64 Tp[NPAIR];
#pragma unroll
    for (int q = 0; q < NQUAD; q++) {
        float t0 = ex2f((0.25f - (v4[q].x - mn) * inv) * SC);
        float t1 = ex2f((0.25f - (v4[q].y - mn) * inv) * SC);
        float t2 = ex2f((0.25f - (v4[q].z - mn) * inv) * SC);
        float t3 = ex2f((0.25f - (v4[q].w - mn) * inv) * SC);
        Tp[2*q]   = pack2(t0, t1);
        Tp[2*q+1] = pack2(t2, t3);
    }

    // ---- one-time phase skew: grp * ~265 cyc dependent-FADD chain ----
    // Groups share no barrier, so this offset persists across the loop and
    // staggers the 4 groups' serial reduction tails (~250 cyc) under each
    // other's compute phases. Deterministic (fixed trip count per grp).
    {
        float zz = 1.0f;
        const int spin = grp * SKEWN;        // ~6 cyc per dependent iter
        for (int i = 0; i < spin; i++)
            asm volatile("add.f32 %0, %0, %1;" : "+f"(zz) : "f"(inv));
        if (zz == -12345.0f)                 // never true; keeps chain alive
            orow[0] = make_float4(zz, zz, zz, zz);
    }

    // ---- Sinkhorn loop: ONE named barrier per iteration ----
    // All threads of the group fold the 4 partials and update E,F,Q with an
    // identical deterministic sequence -> consistent state, no broadcast.
    float E = 1.0f, F = 1.0f, Q = QC;
    float g0 = 0.0f, Qg2 = 0.0f;

    for (int it = 0; it < ITERS; ++it) {
        const u64 Ep = pack2(E, E);
        const u64 Qp = pack2(Q, Q);
        u64 sAp = 0, sRp = 0;
#pragma unroll
        for (int j = 0; j < NPAIR; j++) {
            u64 tp = mulx2(Tp[j], Ep);       // t = T*E
            u64 tq = addx2(tp, Qp);          // t + Q
            u64 dp = fmax2(tp, tp, tq);      // t^2 + t + Q
            float dx, dy; unpack2(dp, dx, dy);
            u64 rp = pack2(rcpf(dx), rcpf(dy));
            sAp = fmax2(tq, rp, sAp);        // += (t+Q)*r
            sRp = addx2(sRp, rp);            // += r
        }
        float ax, ay, rx, ry;
        unpack2(sAp, ax, ay); unpack2(sRp, rx, ry);
        float sA = ax + ay, sR = rx + ry;
#pragma unroll
        for (int off = 16; off; off >>= 1) {
            sA += __shfl_xor_sync(0xffffffffu, sA, off);
            sR += __shfl_xor_sync(0xffffffffu, sR, off);
        }
        const int p = it & 1;
        if (lid == 0) red[p][grp][gwid] = make_float2(sA, sR);
        gbar(barid);

        float2 p0 = red[p][grp][0], p1 = red[p][grp][1];
        float2 p2 = red[p][grp][2], p3 = red[p][grp][3];
        float SA = (p0.x + p1.x) + (p2.x + p3.x);
        float SR = (p0.y + p1.y) + (p2.y + p3.y);

        float S0 = fmaxf((float)NCOLS - SA, 1e-30f);
        float S2 = fmaxf(Q * SR, 1e-30f);
        float S1 = fmaxf(SA - S2, 1e-30f);
        if (it < ITERS - 1) {
            float s  = S1 * 0.16666667163372040f;   // S1/6
            float rc = rcpf(S0 * S2);               // one MUFU, both updates
            E = E * s * (S2 * rc);
            F = F * s * (S0 * rc);
            Q = QC * E * F;
        } else {
            g0  = 512.0f / S0;
            Qg2 = Q * (512.0f / S2);
        }
        // double-buffered red: iter it+2's write to buffer p is separated
        // from iter it's reads by iter it+1's barrier -> 1 barrier/iter.
    }

    // ---- epilogue: out_i = r*(Qg2 - t^2*g0), float4 stores ----
    const u64 Ep = pack2(E, E);
    const u64 Qp = pack2(Q, Q);
#pragma unroll
    for (int q = 0; q < NQUAD; q++) {
        float4 o;
        {
            u64 tp = mulx2(Tp[2*q], Ep);
            u64 tq = addx2(tp, Qp);
            u64 dp = fmax2(tp, tp, tq);
            float dx, dy, tx, ty;
            unpack2(dp, dx, dy); unpack2(tp, tx, ty);
            o.x = rcpf(dx) * fmaf(tx * tx, -g0, Qg2);
            o.y = rcpf(dy) * fmaf(ty * ty, -g0, Qg2);
        }
        {
            u64 tp = mulx2(Tp[2*q+1], Ep);
            u64 tq = addx2(tp, Qp);
            u64 dp = fmax2(tp, tp, tq);
            float dx, dy, tx, ty;
            unpack2(dp, dx, dy); unpack2(tp, tx, ty);
            o.z = rcpf(dx) * fmaf(tx * tx, -g0, Qg2);
            o.w = rcpf(dy) * fmaf(ty * ty, -g0, Qg2);
        }
        orow[gtid + q * GSIZE] = o;
    }
}

extern "C" void kernel_launch(void* const* d_in, const int* in_sizes, int n_in,
                              void* d_out, int out_size)
{
    const float* scores = (const float*)d_in[0];
    float* out = (float*)d_out;
    int rows = in_sizes[0] / NCOLS;                 // 512
    int blocks = (rows + NGROUPS - 1) / NGROUPS;    // 128
    soft_topk_bottomk_kernel<<<blocks, THREADS>>>(scores, out, rows);
}